// round 8
// baseline (speedup 1.0000x reference)
#include <cuda_runtime.h>

// Problem constants (fixed by setup_inputs)
#define BS      16
#define NQ      100
#define JD      51
#define ITILE   12          // rows of the cost matrix per block
#define HALF    6           // i-rows per thread sub-group
#define NTILES  9           // ceil(100/12) -> 9*16 = 144 blocks (one wave on 148 SMs)
#define THREADS 256
#define SPITCH  52          // shared pred row pitch (52*4 = 208 B, 16B aligned)

__global__ __launch_bounds__(THREADS)
void hungarian_cost_kernel(
    const float* __restrict__ pred_conf,    // (16,100,1)
    const float* __restrict__ pred_joint,   // (16,100,51)
    const float* __restrict__ pred_action,  // (16,100,8)
    const float* __restrict__ pred_ident,   // (16,100,10)
    const float* __restrict__ tar_conf,     // (16,100)
    const float* __restrict__ tar_joint,    // (16,100,51)
    float* __restrict__ out)                // (16,100,100)
{
    __shared__ __align__(16) float s_pred[ITILE * SPITCH];
    __shared__ float sA[ITILE];   // log p - log(1-p)
    __shared__ float sB[ITILE];   // log(1-p)
    __shared__ float sRC[ITILE];  // ce_action + ce_identity

    const int b    = blockIdx.y;
    const int i0   = blockIdx.x * ITILE;
    const int rows = min(ITILE, NQ - i0);
    const int tid  = threadIdx.x;

    // ---- per-row constants (12 threads, trivially cheap) ----
    if (tid < rows) {
        const int n = b * NQ + i0 + tid;

        // stable log-sigmoid pair: log p = -log1p(e^-x), log(1-p) = -log1p(e^x)
        const float x      = pred_conf[n];
        const float logp   = -log1pf(expf(-x));
        const float log1mp = -log1pf(expf(x));

        // ce_a = logsumexp(action) - action[0]
        const float* a = pred_action + n * 8;
        float m = a[0];
        #pragma unroll
        for (int k = 1; k < 8; k++) m = fmaxf(m, a[k]);
        float s = 0.f;
        #pragma unroll
        for (int k = 0; k < 8; k++) s += expf(a[k] - m);
        const float cea = m + logf(s) - a[0];

        // ce_i = logsumexp(identity) - identity[0]
        const float* c = pred_ident + n * 10;
        float m2 = c[0];
        #pragma unroll
        for (int k = 1; k < 10; k++) m2 = fmaxf(m2, c[k]);
        float s2 = 0.f;
        #pragma unroll
        for (int k = 0; k < 10; k++) s2 += expf(c[k] - m2);
        const float cei = m2 + logf(s2) - c[0];

        sA[tid]  = logp - log1mp;
        sB[tid]  = log1mp;
        sRC[tid] = cea + cei;
    }

    // ---- stage pred_joint tile into shared (coalesced), pitch 52 ----
    for (int idx = tid; idx < rows * JD; idx += THREADS) {
        const int ii = idx / JD;
        const int k  = idx - ii * JD;
        s_pred[ii * SPITCH + k] = pred_joint[(b * NQ + i0) * JD + idx];
    }
    __syncthreads();

    // ---- main compute: thread = (j, i-half) ----
    const int j   = tid & 127;
    const int sub = tid >> 7;
    if (j < NQ) {
        const int nj = b * NQ + j;
        const float tj = tar_conf[nj];

        // tar_joint row resident in registers (51 regs)
        float r[JD];
        const float* trow = tar_joint + nj * JD;
        #pragma unroll
        for (int k = 0; k < JD; k++) r[k] = __ldg(trow + k);

        const int ibeg = sub * HALF;
        const int iend = min(rows, ibeg + HALF);
        for (int ii = ibeg; ii < iend; ii++) {
            const float4* row4 = reinterpret_cast<const float4*>(s_pred + ii * SPITCH);
            float a0 = 0.f, a1 = 0.f, a2 = 0.f, a3 = 0.f;
            #pragma unroll
            for (int q = 0; q < 12; q++) {      // 48 of 51 elements, LDS.128 broadcast
                const float4 v = row4[q];
                a0 += fabsf(r[4 * q + 0] - v.x);
                a1 += fabsf(r[4 * q + 1] - v.y);
                a2 += fabsf(r[4 * q + 2] - v.z);
                a3 += fabsf(r[4 * q + 3] - v.w);
            }
            a0 += fabsf(r[48] - s_pred[ii * SPITCH + 48]);
            a1 += fabsf(r[49] - s_pred[ii * SPITCH + 49]);
            a2 += fabsf(r[50] - s_pred[ii * SPITCH + 50]);

            const float joint = (a0 + a1) + (a2 + a3);
            // cost = rc + joint - ( B + t*A )   [== rc + joint + C_prob]
            const float res = sRC[ii] + joint - sB[ii] - tj * sA[ii];
            out[(b * NQ + i0 + ii) * NQ + j] = res;
        }
    }
}

extern "C" void kernel_launch(void* const* d_in, const int* in_sizes, int n_in,
                              void* d_out, int out_size)
{
    (void)in_sizes; (void)n_in; (void)out_size;
    const dim3 grid(NTILES, BS);
    hungarian_cost_kernel<<<grid, THREADS>>>(
        (const float*)d_in[0],   // pred_conf
        (const float*)d_in[1],   // pred_joint
        (const float*)d_in[2],   // pred_action
        (const float*)d_in[3],   // pred_identity
        (const float*)d_in[4],   // tar_conf
        (const float*)d_in[5],   // tar_joint
        (float*)d_out);
    // d_in[6] (tar_action) and d_in[7] (tar_identity) are unused by the
    // reference (it takes log_softmax[:, 0], not a gather).
}

// round 9
// speedup vs baseline: 1.0295x; 1.0295x over previous
#include <cuda_runtime.h>

// Problem constants (fixed by setup_inputs)
#define BS      16
#define NQ      100
#define JD      51
#define ITILE   12          // rows of the cost matrix per block
#define HALF    6           // i-rows per thread sub-group
#define NTILES  9           // ceil(100/12) -> 9*16 = 144 blocks (one wave on 148 SMs)
#define THREADS 256
#define SPITCH  52          // shared pred row pitch (52*4 = 208 B, 16B aligned)

__global__ __launch_bounds__(THREADS)
void hungarian_cost_kernel(
    const float* __restrict__ pred_conf,    // (16,100,1)
    const float* __restrict__ pred_joint,   // (16,100,51)
    const float* __restrict__ pred_action,  // (16,100,8)
    const float* __restrict__ pred_ident,   // (16,100,10)
    const float* __restrict__ tar_conf,     // (16,100)
    const float* __restrict__ tar_joint,    // (16,100,51)
    float* __restrict__ out)                // (16,100,100)
{
    __shared__ __align__(16) float s_pred[ITILE * SPITCH];
    __shared__ float sA[ITILE];   // log p - log(1-p)
    __shared__ float sB[ITILE];   // log(1-p)
    __shared__ float sRC[ITILE];  // ce_action + ce_identity

    const int b    = blockIdx.y;
    const int i0   = blockIdx.x * ITILE;
    const int rows = min(ITILE, NQ - i0);
    const int tid  = threadIdx.x;

    // ---- per-row constants (12 threads, trivially cheap) ----
    if (tid < rows) {
        const int n = b * NQ + i0 + tid;

        // stable log-sigmoid pair: log p = -log1p(e^-x), log(1-p) = -log1p(e^x)
        const float x      = pred_conf[n];
        const float logp   = -log1pf(expf(-x));
        const float log1mp = -log1pf(expf(x));

        // ce_a = logsumexp(action) - action[0]
        const float* a = pred_action + n * 8;
        float m = a[0];
        #pragma unroll
        for (int k = 1; k < 8; k++) m = fmaxf(m, a[k]);
        float s = 0.f;
        #pragma unroll
        for (int k = 0; k < 8; k++) s += expf(a[k] - m);
        const float cea = m + logf(s) - a[0];

        // ce_i = logsumexp(identity) - identity[0]
        const float* c = pred_ident + n * 10;
        float m2 = c[0];
        #pragma unroll
        for (int k = 1; k < 10; k++) m2 = fmaxf(m2, c[k]);
        float s2 = 0.f;
        #pragma unroll
        for (int k = 0; k < 10; k++) s2 += expf(c[k] - m2);
        const float cei = m2 + logf(s2) - c[0];

        sA[tid]  = logp - log1mp;
        sB[tid]  = log1mp;
        sRC[tid] = cea + cei;
    }

    // ---- stage pred_joint tile into shared (coalesced), pitch 52 ----
    for (int idx = tid; idx < rows * JD; idx += THREADS) {
        const int ii = idx / JD;
        const int k  = idx - ii * JD;
        s_pred[ii * SPITCH + k] = pred_joint[(b * NQ + i0) * JD + idx];
    }
    __syncthreads();

    // ---- main compute: thread = (j, i-half) ----
    const int j   = tid & 127;
    const int sub = tid >> 7;
    if (j < NQ) {
        const int nj = b * NQ + j;
        const float tj = tar_conf[nj];

        // tar_joint row resident in registers (51 regs)
        float r[JD];
        const float* trow = tar_joint + nj * JD;
        #pragma unroll
        for (int k = 0; k < JD; k++) r[k] = __ldg(trow + k);

        const int ibeg = sub * HALF;
        const int iend = min(rows, ibeg + HALF);
        for (int ii = ibeg; ii < iend; ii++) {
            const float4* row4 = reinterpret_cast<const float4*>(s_pred + ii * SPITCH);
            float a0 = 0.f, a1 = 0.f, a2 = 0.f, a3 = 0.f;
            #pragma unroll
            for (int q = 0; q < 12; q++) {      // 48 of 51 elements, LDS.128 broadcast
                const float4 v = row4[q];
                a0 += fabsf(r[4 * q + 0] - v.x);
                a1 += fabsf(r[4 * q + 1] - v.y);
                a2 += fabsf(r[4 * q + 2] - v.z);
                a3 += fabsf(r[4 * q + 3] - v.w);
            }
            a0 += fabsf(r[48] - s_pred[ii * SPITCH + 48]);
            a1 += fabsf(r[49] - s_pred[ii * SPITCH + 49]);
            a2 += fabsf(r[50] - s_pred[ii * SPITCH + 50]);

            const float joint = (a0 + a1) + (a2 + a3);
            // cost = rc + joint - ( B + t*A )   [== rc + joint + C_prob]
            const float res = sRC[ii] + joint - sB[ii] - tj * sA[ii];
            out[(b * NQ + i0 + ii) * NQ + j] = res;
        }
    }
}

extern "C" void kernel_launch(void* const* d_in, const int* in_sizes, int n_in,
                              void* d_out, int out_size)
{
    (void)in_sizes; (void)n_in; (void)out_size;
    const dim3 grid(NTILES, BS);
    hungarian_cost_kernel<<<grid, THREADS>>>(
        (const float*)d_in[0],   // pred_conf
        (const float*)d_in[1],   // pred_joint
        (const float*)d_in[2],   // pred_action
        (const float*)d_in[3],   // pred_identity
        (const float*)d_in[4],   // tar_conf
        (const float*)d_in[5],   // tar_joint
        (float*)d_out);
    // d_in[6] (tar_action) and d_in[7] (tar_identity) are unused by the
    // reference (it takes log_softmax[:, 0], not a gather).
}